// round 15
// baseline (speedup 1.0000x reference)
#include <cuda_runtime.h>

// ---------------------------------------------------------------------------
// PC_RNN_HC_A round 13: 8 independent row-groups x 16 CTAs, group-local
// barriers (batch rows never mix across GEMMs -> no global sync needed),
// cp.async double-buffered smem for both operands, FFMA2 packed math.
// ---------------------------------------------------------------------------

#define GRID      128
#define NTHREADS  256
#define NGROUP    16      // CTAs per row-group
#define NGROUPS   8

#define SEQ   512
#define BATCH 256
#define OUTD  256
#define CAUS  64
#define HID   512

#define SB 68             // conflict-free smem row stride (floats)
#define BUFSZ (32 * SB)   // one buffer = up to 32 rows

typedef unsigned long long u64;

// Persistent state (device globals; allocation forbidden)
__device__ float g_h  [BATCH * HID];
__device__ float g_th [BATCH * HID];
__device__ float g_hp [BATCH * HID];
__device__ float g_tp [BATCH * HID];
__device__ float g_eh [BATCH * HID];
__device__ float g_err[BATCH * OUTD];
__device__ float g_c  [BATCH * CAUS];
__device__ float g_woT[HID * OUTD];   // woT[i][o] = w_o[o][i]
__device__ float g_wcT[CAUS * HID];   // wcT[c][i] = w_c[i][c]

// Barriers: one global (init only) + 8 group-local, 256B apart (distinct LTS)
__device__ unsigned g_bar_count;
__device__ unsigned g_bar_gen;
__device__ unsigned g_cnt[NGROUPS * 64];
__device__ unsigned g_gen[NGROUPS * 64];

// ---------------------------------------------------------------------------
// Global barrier (init only; monotone generation; replay-safe)
// ---------------------------------------------------------------------------
__device__ __forceinline__ void barrier_global() {
    __syncthreads();
    if (threadIdx.x == 0) {
        volatile unsigned* genp = &g_bar_gen;
        unsigned my = *genp;
        __threadfence();
        unsigned prev = atomicAdd(&g_bar_count, 1u);
        if (prev == GRID - 1u) {
            g_bar_count = 0u;
            __threadfence();
            atomicExch(&g_bar_gen, my + 1u);
        } else {
            while (*genp == my) { }
            __threadfence();
        }
    }
    __syncthreads();
}

// ---------------------------------------------------------------------------
// Group barrier: 16 CTAs of one row-group. Call after __syncthreads() (and
// optional prefetch issue). threadfence (gpu scope) flushes/invalidates L1D,
// ordering cross-SM data through L2 on both sides.
// ---------------------------------------------------------------------------
__device__ __forceinline__ void group_sync(int g) {
    if (threadIdx.x == 0) {
        volatile unsigned* genp = &g_gen[g * 64];
        unsigned my = *genp;
        __threadfence();
        unsigned prev = atomicAdd(&g_cnt[g * 64], 1u);
        if (prev == NGROUP - 1u) {
            g_cnt[g * 64] = 0u;
            __threadfence();
            atomicExch((unsigned*)&g_gen[g * 64], my + 1u);
        } else {
            while (*genp == my) { }
            __threadfence();
        }
    }
    __syncthreads();
}

// ---------------------------------------------------------------------------
// Packed f32x2 FMA (SASS FFMA2; PTX-only form)
// ---------------------------------------------------------------------------
__device__ __forceinline__ void ffma2(u64 &acc, u64 a, u64 b) {
    asm("fma.rn.f32x2 %0, %1, %2, %0;" : "+l"(acc) : "l"(a), "l"(b));
}
__device__ __forceinline__ float fsum2(u64 v) {
    float lo, hi;
    asm("mov.b64 {%0,%1}, %2;" : "=f"(lo), "=f"(hi) : "l"(v));
    return lo + hi;
}

// ---------------------------------------------------------------------------
// cp.async helpers
// ---------------------------------------------------------------------------
__device__ __forceinline__ void cp_async16(float* s, const float* g) {
    unsigned sa = (unsigned)__cvta_generic_to_shared(s);
    asm volatile("cp.async.ca.shared.global [%0], [%1], 16;" :: "r"(sa), "l"(g));
}
__device__ __forceinline__ void cp_commit() { asm volatile("cp.async.commit_group;"); }
__device__ __forceinline__ void cp_wait0()  { asm volatile("cp.async.wait_group 0;"); }

// Fill a TR-row x 64-k tile from k-major source (leading dim ldb).
template<int TR>
__device__ __forceinline__ void fill_t(float* s, const float* __restrict__ B,
                                       int ldb, int k0) {
    const int tid = threadIdx.x;
    constexpr int TOT = TR * 16;
    if (TOT >= NTHREADS) {
#pragma unroll
        for (int it = 0; it < TOT / NTHREADS; it++) {
            int idx = tid + it * NTHREADS;
            int n = idx >> 4, k4 = idx & 15;
            cp_async16(s + n * SB + k4 * 4, B + n * ldb + k0 + k4 * 4);
        }
    } else if (tid < TOT) {
        int n = tid >> 4, k4 = tid & 15;
        cp_async16(s + n * SB + k4 * 4, B + n * ldb + k0 + k4 * 4);
    }
}

// ---------------------------------------------------------------------------
// Smem-smem NT GEMM. Precondition: B k-tile 0 already cp.async-committed into
// sb buffer 0 (issued before the preceding barrier). A k-tile 0 filled here.
// Both operands double-buffered; compute is pure LDS + FFMA2.
// ---------------------------------------------------------------------------
template<int RM, int RN>
__device__ __forceinline__ void gemm_ss(float* sa, float* sb,
                                        const float* __restrict__ A, int lda,
                                        const float* __restrict__ B, int ldb,
                                        int ktiles, u64 (&acc)[RM][RN]) {
    constexpr int TM = 16 * RM, TN = 16 * RN;
    const int tx = threadIdx.x & 15, ty = threadIdx.x >> 4;

    fill_t<TM>(sa, A, lda, 0);
    cp_commit();

    int buf = 0;
    for (int kt = 0; kt < ktiles; kt++) {
        cp_wait0();
        __syncthreads();
        if (kt + 1 < ktiles) {
            fill_t<TM>(sa + (buf ^ 1) * BUFSZ, A, lda, (kt + 1) * 64);
            fill_t<TN>(sb + (buf ^ 1) * BUFSZ, B, ldb, (kt + 1) * 64);
            cp_commit();
        }
        const float* as = sa + buf * BUFSZ;
        const float* bs = sb + buf * BUFSZ;
#pragma unroll
        for (int k4 = 0; k4 < 16; k4++) {
            ulonglong2 a2[RM], b2[RN];
#pragma unroll
            for (int im = 0; im < RM; im++)
                a2[im] = *reinterpret_cast<const ulonglong2*>(as + (ty + 16 * im) * SB + k4 * 4);
#pragma unroll
            for (int in = 0; in < RN; in++)
                b2[in] = *reinterpret_cast<const ulonglong2*>(bs + (tx + 16 * in) * SB + k4 * 4);
#pragma unroll
            for (int im = 0; im < RM; im++)
#pragma unroll
                for (int in = 0; in < RN; in++) {
                    ffma2(acc[im][in], a2[im].x, b2[in].x);
                    ffma2(acc[im][in], a2[im].y, b2[in].y);
                }
        }
        buf ^= 1;
    }
}

// ---------------------------------------------------------------------------
// Main persistent kernel (1 CTA/SM)
// ---------------------------------------------------------------------------
__global__ void __launch_bounds__(NTHREADS, 1)
pc_rnn_kernel(const float* __restrict__ x,
              const float* __restrict__ c_init,
              const float* __restrict__ h_init,
              const float* __restrict__ w_o,
              const float* __restrict__ b_o,
              const float* __restrict__ w_c,
              const float* __restrict__ w_r,
              const float* __restrict__ b_r,
              float* __restrict__ out) {
    __shared__ float s_a[2 * BUFSZ];   // A operand double buffer (17408 B)
    __shared__ float s_b[2 * BUFSZ];   // B operand double buffer (17408 B)

    const int bid = blockIdx.x;
    const int tid = threadIdx.x;
    const int tx  = tid & 15, ty = tid >> 4;
    const int gtid = bid * NTHREADS + tid;
    const int gstride = GRID * NTHREADS;

    // Row-group decomposition: 8 groups x 16 CTAs; 32 batch rows per group.
    const int grp  = bid >> 4;          // 0..7
    const int q    = bid & 15;          // lane within group
    const int row0 = grp * 32;          // this group's batch rows
    const int colA = q * 32;            // phase A/C column block (of 512)
    const int colB = q * 16;            // phase B column block (of 256)
    const int rowD = row0 + (q >> 2) * 8;   // phase D: 4x4 tiling of 32x64
    const int colD = (q & 3) * 16;

    // ---- init state + weight transposes (grid-wide; fresh every replay) ----
    for (int i = gtid; i < BATCH * HID; i += gstride) {
        float h = h_init[i];
        g_h[i]  = h;
        g_th[i] = tanhf(h);
    }
    for (int i = gtid; i < BATCH * CAUS; i += gstride)
        g_c[i] = c_init[i];
    for (int i = gtid; i < HID * OUTD; i += gstride) {   // woT[i][o] = w_o[o][i]
        int hh = i >> 8, o = i & (OUTD - 1);
        g_woT[i] = w_o[o * HID + hh];
    }
    for (int i = gtid; i < CAUS * HID; i += gstride) {   // wcT[c][i] = w_c[i][c]
        int c = i >> 9, hh = i & (HID - 1);
        g_wcT[i] = w_c[hh * CAUS + c];
    }
    __syncthreads();
    fill_t<32>(s_b, w_r + colA * HID, HID, 0);   // prefetch phase-A weights
    cp_commit();
    barrier_global();                            // once per launch

    for (int t = 0; t < SEQ; t++) {
        // ---- Phase A: h_prior = 0.9*h + 0.1*(th@Wr^T + c@Wc^T + b_r); tp ----
        {
            u64 acc[2][2] = {};
            gemm_ss<2, 2>(s_a, s_b, g_th + row0 * HID, HID,
                          w_r + colA * HID, HID, HID / 64, acc);
            // c @ Wc^T part: single k-tile into buffer 0 (stragglers of the
            // loop above only read buffer 1 -> safe)
            fill_t<32>(s_a, g_c + row0 * CAUS, CAUS, 0);
            fill_t<32>(s_b, w_c + colA * CAUS, CAUS, 0);
            cp_commit();
            cp_wait0();
            __syncthreads();
#pragma unroll
            for (int k4 = 0; k4 < 16; k4++) {
                ulonglong2 a2[2], b2[2];
#pragma unroll
                for (int im = 0; im < 2; im++)
                    a2[im] = *reinterpret_cast<const ulonglong2*>(s_a + (ty + 16 * im) * SB + k4 * 4);
#pragma unroll
                for (int in = 0; in < 2; in++)
                    b2[in] = *reinterpret_cast<const ulonglong2*>(s_b + (tx + 16 * in) * SB + k4 * 4);
#pragma unroll
                for (int im = 0; im < 2; im++)
#pragma unroll
                    for (int in = 0; in < 2; in++) {
                        ffma2(acc[im][in], a2[im].x, b2[in].x);
                        ffma2(acc[im][in], a2[im].y, b2[in].y);
                    }
            }
#pragma unroll
            for (int im = 0; im < 2; im++)
#pragma unroll
                for (int in = 0; in < 2; in++) {
                    int r   = row0 + ty + 16 * im;
                    int ci  = colA + tx + 16 * in;
                    int idx = r * HID + ci;
                    float hp = 0.9f * g_h[idx] + 0.1f * (fsum2(acc[im][in]) + b_r[ci]);
                    g_hp[idx] = hp;
                    g_tp[idx] = tanhf(hp);
                }
        }
        __syncthreads();                              // buffer-0 readers done
        fill_t<16>(s_b, w_o + colB * HID, HID, 0);    // prefetch phase-B weights
        cp_commit();
        group_sync(grp);

        // ---- Phase B: err = tp@Wo^T + b_o - x_t  (streamed to out too) ----
        {
            u64 acc[2][1] = {};
            gemm_ss<2, 1>(s_a, s_b, g_tp + row0 * HID, HID,
                          w_o + colB * HID, HID, HID / 64, acc);
#pragma unroll
            for (int im = 0; im < 2; im++) {
                int r  = row0 + ty + 16 * im;
                int o  = colB + tx;
                int xi = (t * BATCH + r) * OUTD + o;
                float e = fsum2(acc[im][0]) + b_o[o] - x[xi];
                g_err[r * OUTD + o] = e;
                out[xi] = e;
            }
        }
        __syncthreads();
        fill_t<32>(s_b, g_woT + colA * OUTD, OUTD, 0);  // prefetch phase-C weights
        cp_commit();
        group_sync(grp);

        // ---- Phase C: gvec = err@woT; eh = 0.1*(1-tp^2)*gvec; h_post; th ----
        {
            u64 acc[2][2] = {};
            gemm_ss<2, 2>(s_a, s_b, g_err + row0 * OUTD, OUTD,
                          g_woT + colA * OUTD, OUTD, OUTD / 64, acc);
#pragma unroll
            for (int im = 0; im < 2; im++)
#pragma unroll
                for (int in = 0; in < 2; in++) {
                    int r   = row0 + ty + 16 * im;
                    int ci  = colA + tx + 16 * in;
                    int idx = r * HID + ci;
                    float tp = g_tp[idx];
                    float eh = 0.1f * (1.0f - tp * tp) * fsum2(acc[im][in]);
                    float hpost = g_hp[idx] - eh;
                    g_eh[idx] = eh;
                    g_h[idx]  = hpost;
                    g_th[idx] = tanhf(hpost);
                }
        }
        __syncthreads();
        fill_t<16>(s_b, g_wcT + colD * HID, HID, 0);    // prefetch phase-D weights
        cp_commit();
        group_sync(grp);

        // ---- Phase D: c -= 0.1 * (eh @ Wc)  (via wcT); 8x16 tile per CTA ----
        {
            fill_t<8>(s_a, g_eh + rowD * HID, HID, 0);
            cp_commit();
            u64 accD = 0ull;
            int buf = 0;
            for (int kt = 0; kt < 8; kt++) {
                cp_wait0();
                __syncthreads();
                if (kt < 7) {
                    fill_t<8>(s_a + (buf ^ 1) * BUFSZ, g_eh + rowD * HID, HID, (kt + 1) * 64);
                    fill_t<16>(s_b + (buf ^ 1) * BUFSZ, g_wcT + colD * HID, HID, (kt + 1) * 64);
                    cp_commit();
                }
                if (tid < 128) {
                    const float* as = s_a + buf * BUFSZ + (ty & 7) * SB;
                    const float* bs = s_b + buf * BUFSZ + tx * SB;
#pragma unroll
                    for (int k4 = 0; k4 < 16; k4++) {
                        ulonglong2 a = *reinterpret_cast<const ulonglong2*>(as + k4 * 4);
                        ulonglong2 b = *reinterpret_cast<const ulonglong2*>(bs + k4 * 4);
                        ffma2(accD, a.x, b.x);
                        ffma2(accD, a.y, b.y);
                    }
                }
                buf ^= 1;
            }
            if (tid < 128)
                g_c[(rowD + (ty & 7)) * CAUS + colD + tx] -= 0.1f * fsum2(accD);
        }
        __syncthreads();
        fill_t<32>(s_b, w_r + colA * HID, HID, 0);      // prefetch next step's A
        cp_commit();
        group_sync(grp);
    }
}

// ---------------------------------------------------------------------------
// Launch: single graph-capturable kernel node, no allocation.
// Inputs (metadata order): x, c_init, h_init, w_o, b_o, w_c, w_r, b_r
// ---------------------------------------------------------------------------
extern "C" void kernel_launch(void* const* d_in, const int* in_sizes, int n_in,
                              void* d_out, int out_size) {
    const float* x      = (const float*)d_in[0];
    const float* c_init = (const float*)d_in[1];
    const float* h_init = (const float*)d_in[2];
    const float* w_o    = (const float*)d_in[3];
    const float* b_o    = (const float*)d_in[4];
    const float* w_c    = (const float*)d_in[5];
    const float* w_r    = (const float*)d_in[6];
    const float* b_r    = (const float*)d_in[7];
    float* out = (float*)d_out;

    pc_rnn_kernel<<<GRID, NTHREADS>>>(x, c_init, h_init, w_o, b_o, w_c, w_r, b_r, out);
}

// round 16
// speedup vs baseline: 1.1613x; 1.1613x over previous
#include <cuda_runtime.h>

// ---------------------------------------------------------------------------
// PC_RNN_HC_A round 15: weights RESIDENT in smem (loaded once), activations
// via single cp.async.bulk (TMA) per phase + mbarrier, state carried in
// registers, phase D folded into phase C as deterministic split-i partials.
// Rationale: LDGSTS costs 8 cyc/op/SMSP -> per-step 16B cp.async fills were
// the real wall (~20 us/step of copy issue). TMA bulk has ~zero issue cost.
// ---------------------------------------------------------------------------

#define GRID      128
#define NTHREADS  256

#define SEQ   512
#define BATCH 256
#define OUTD  256
#define CAUS  64
#define HID   512

typedef unsigned long long u64;

// ---- dynamic smem layout (floats) ----
#define OFF_MBAR 0
#define OFF_WR   4
#define SWR      516                       // 512 + 4 pad (conflict-free)
#define OFF_WC   (OFF_WR + 32 * SWR)
#define SWC      68
#define OFF_WO   (OFF_WC + 32 * SWC)
#define SWO      516
#define OFF_WOT  (OFF_WO + 16 * SWO)
#define SWOT     260
#define OFF_EHS  (OFF_WOT + 32 * SWOT)
#define SEH      33
#define OFF_ACT  (OFF_EHS + 32 * SEH + 12) // padded to 16B boundary
#define ACT_FL   18432                     // max: 32x512 + 32x64 (phase A)
#define SMEM_FL  (OFF_ACT + ACT_FL)
#define SMEM_BYTES (SMEM_FL * 4)           // 219072 B  (< 227KB limit)

// ---- persistent gmem state (device globals; allocation forbidden) ----
__device__ float g_th [BATCH * HID];    // tanh(h_post)
__device__ float g_tp [BATCH * HID];    // tanh(h_prior)
__device__ float g_err[BATCH * OUTD];
__device__ float g_c  [BATCH * CAUS];
__device__ float g_dpart[GRID * 32 * 64];  // phase-D partials (per CTA)

__device__ unsigned g_bar_count;        // zero at module load
__device__ unsigned g_bar_gen;

// ---------------------------------------------------------------------------
// Grid barrier (R10 proven form; monotone generation; replay-safe)
// ---------------------------------------------------------------------------
__device__ __forceinline__ void barrier_global() {
    __syncthreads();
    if (threadIdx.x == 0) {
        volatile unsigned* genp = &g_bar_gen;
        unsigned my = *genp;
        __threadfence();
        unsigned prev = atomicAdd(&g_bar_count, 1u);
        if (prev == GRID - 1u) {
            g_bar_count = 0u;
            __threadfence();
            atomicExch(&g_bar_gen, my + 1u);
        } else {
            while (*genp == my) { }
            __threadfence();
        }
    }
    __syncthreads();
}

// ---------------------------------------------------------------------------
// Packed f32x2 FMA (SASS FFMA2; PTX-only form)
// ---------------------------------------------------------------------------
__device__ __forceinline__ void ffma2(u64 &acc, u64 a, u64 b) {
    asm("fma.rn.f32x2 %0, %1, %2, %0;" : "+l"(acc) : "l"(a), "l"(b));
}
__device__ __forceinline__ float fsum2(u64 v) {
    float lo, hi;
    asm("mov.b64 {%0,%1}, %2;" : "=f"(lo), "=f"(hi) : "l"(v));
    return lo + hi;
}

// ---------------------------------------------------------------------------
// TMA bulk 1D + mbarrier helpers
// ---------------------------------------------------------------------------
__device__ __forceinline__ unsigned s2u(const void* p) {
    return (unsigned)__cvta_generic_to_shared(p);
}
__device__ __forceinline__ void mbar_init(unsigned mbar) {
    asm volatile("mbarrier.init.shared.b64 [%0], 1;" :: "r"(mbar) : "memory");
}
__device__ __forceinline__ void fence_pa() {
    asm volatile("fence.proxy.async.shared::cta;" ::: "memory");
}
__device__ __forceinline__ void mbar_expect(unsigned mbar, unsigned bytes) {
    asm volatile("mbarrier.arrive.expect_tx.shared.b64 _, [%0], %1;"
                 :: "r"(mbar), "r"(bytes) : "memory");
}
__device__ __forceinline__ void bulk_g2s(unsigned dst, const void* src,
                                         unsigned bytes, unsigned mbar) {
    asm volatile(
        "cp.async.bulk.shared::cta.global.mbarrier::complete_tx::bytes "
        "[%0], [%1], %2, [%3];"
        :: "r"(dst), "l"(src), "r"(bytes), "r"(mbar) : "memory");
}
__device__ __forceinline__ void mbar_wait(unsigned mbar, unsigned parity) {
    asm volatile(
        "{\n\t"
        ".reg .pred P;\n\t"
        "WL%=:\n\t"
        "mbarrier.try_wait.parity.acquire.cta.shared::cta.b64 P, [%0], %1, 0x989680;\n\t"
        "@P bra WD%=;\n\t"
        "bra WL%=;\n\t"
        "WD%=:\n\t"
        "}"
        :: "r"(mbar), "r"(parity) : "memory");
}

// ---------------------------------------------------------------------------
// Resident GEMM: acc[im][in] += A[ty+16im][k] * B[tx+16in][k], both in smem.
// No syncs, no fills — pure LDS + FFMA2. A unpadded (broadcast reads),
// B padded stride (conflict-free).
// ---------------------------------------------------------------------------
template<int RM, int RN>
__device__ __forceinline__ void gemm_res(const float* A, int lda,
                                         const float* B, int ldb,
                                         int ktiles, u64 (&acc)[RM][RN],
                                         int ty, int tx) {
    for (int kt = 0; kt < ktiles; kt++) {
        const int kb = kt * 64;
#pragma unroll
        for (int k4 = 0; k4 < 16; k4++) {
            ulonglong2 a2[RM], b2[RN];
#pragma unroll
            for (int im = 0; im < RM; im++)
                a2[im] = *reinterpret_cast<const ulonglong2*>(A + (ty + 16 * im) * lda + kb + k4 * 4);
#pragma unroll
            for (int in = 0; in < RN; in++)
                b2[in] = *reinterpret_cast<const ulonglong2*>(B + (tx + 16 * in) * ldb + kb + k4 * 4);
#pragma unroll
            for (int im = 0; im < RM; im++)
#pragma unroll
                for (int in = 0; in < RN; in++) {
                    ffma2(acc[im][in], a2[im].x, b2[in].x);
                    ffma2(acc[im][in], a2[im].y, b2[in].y);
                }
        }
    }
}

// ---------------------------------------------------------------------------
// Main persistent kernel (1 CTA/SM, 214KB dynamic smem)
// ---------------------------------------------------------------------------
__global__ void __launch_bounds__(NTHREADS, 1)
pc_rnn_kernel(const float* __restrict__ x,
              const float* __restrict__ c_init,
              const float* __restrict__ h_init,
              const float* __restrict__ w_o,
              const float* __restrict__ b_o,
              const float* __restrict__ w_c,
              const float* __restrict__ w_r,
              const float* __restrict__ b_r,
              float* __restrict__ out) {
    extern __shared__ float sm[];

    const int bid = blockIdx.x;
    const int tid = threadIdx.x;
    const int tx  = tid & 15, ty = tid >> 4;
    const int gtid = bid * NTHREADS + tid;
    const int gstride = GRID * NTHREADS;

    // Row-group decomposition: 8 groups x 16 CTAs; 32 batch rows per group.
    const int grp  = bid >> 4;
    const int q    = bid & 15;
    const int row0 = grp * 32;
    const int colA = q * 32;    // phase A/C hidden-col block
    const int colB = q * 16;    // phase B out-col block

    const unsigned mbar = s2u(sm + OFF_MBAR);
    const unsigned actu = s2u(sm + OFF_ACT);

    if (tid == 0) mbar_init(mbar);

    // ---- gmem state init (grid-strided; fresh every launch/replay) ----
    for (int i = gtid; i < BATCH * HID; i += gstride)
        g_th[i] = tanhf(h_init[i]);
    for (int i = gtid; i < BATCH * CAUS; i += gstride)
        g_c[i] = c_init[i];

    // ---- resident weight slices (once per launch) ----
    for (int idx = tid; idx < 32 * 512; idx += NTHREADS) {       // w_r rows colA..+31
        int n = idx >> 9, k = idx & 511;
        sm[OFF_WR + n * SWR + k] = w_r[(colA + n) * HID + k];
    }
    for (int idx = tid; idx < 32 * 64; idx += NTHREADS) {        // w_c rows colA..+31
        int n = idx >> 6, k = idx & 63;
        sm[OFF_WC + n * SWC + k] = w_c[(colA + n) * CAUS + k];
    }
    for (int idx = tid; idx < 16 * 512; idx += NTHREADS) {       // w_o rows colB..+15
        int n = idx >> 9, k = idx & 511;
        sm[OFF_WO + n * SWO + k] = w_o[(colB + n) * HID + k];
    }
    for (int idx = tid; idx < 32 * 256; idx += NTHREADS) {       // woT rows colA..+31
        int n = idx >> 8, o = idx & 255;
        sm[OFF_WOT + n * SWOT + o] = w_o[o * HID + colA + n];
    }

    // ---- per-thread register state ----
    float brr[2], bo;
    brr[0] = b_r[colA + tx];
    brr[1] = b_r[colA + tx + 16];
    bo     = b_o[colB + tx];
    float hpost[2][2];                       // h_post carried across steps
#pragma unroll
    for (int im = 0; im < 2; im++)
#pragma unroll
        for (int in = 0; in < 2; in++)
            hpost[im][in] = h_init[(row0 + ty + 16 * im) * HID + colA + tx + 16 * in];

    barrier_global();
    unsigned ph = 0;

    for (int t = 0; t < SEQ; t++) {
        float hpr[2][2], tpr[2][2];

        // ================= Phase A =================
        // h_prior = 0.9*h_post + 0.1*(th@Wr^T + c@Wc^T + b_r); tp = tanh(h_prior)
        {
            if (tid == 0) {
                fence_pa();
                mbar_expect(mbar, 65536 + 8192);
                bulk_g2s(actu, g_th + row0 * HID, 65536, mbar);
                bulk_g2s(actu + 65536, g_c + row0 * CAUS, 8192, mbar);
            }
            mbar_wait(mbar, ph); ph ^= 1;

            u64 acc[2][2] = {};
            gemm_res<2, 2>(sm + OFF_ACT, HID, sm + OFF_WR, SWR, 8, acc, ty, tx);
            gemm_res<2, 2>(sm + OFF_ACT + 16384, CAUS, sm + OFF_WC, SWC, 1, acc, ty, tx);
#pragma unroll
            for (int im = 0; im < 2; im++)
#pragma unroll
                for (int in = 0; in < 2; in++) {
                    float hp = 0.9f * hpost[im][in] + 0.1f * (fsum2(acc[im][in]) + brr[in]);
                    float tp = tanhf(hp);
                    hpr[im][in] = hp;
                    tpr[im][in] = tp;
                    g_tp[(row0 + ty + 16 * im) * HID + colA + tx + 16 * in] = tp;
                }
        }
        barrier_global();

        // ================= Phase B =================
        // err = tp@Wo^T + b_o - x_t  (streamed to out too)
        {
            const int r0 = row0 + ty;
            const int o  = colB + tx;
            float xv0 = x[(t * BATCH + r0) * OUTD + o];        // prefetch early
            float xv1 = x[(t * BATCH + r0 + 16) * OUTD + o];
            if (tid == 0) {
                fence_pa();
                mbar_expect(mbar, 65536);
                bulk_g2s(actu, g_tp + row0 * HID, 65536, mbar);
            }
            mbar_wait(mbar, ph); ph ^= 1;

            u64 acc[2][1] = {};
            gemm_res<2, 1>(sm + OFF_ACT, HID, sm + OFF_WO, SWO, 8, acc, ty, tx);
            float e0 = fsum2(acc[0][0]) + bo - xv0;
            float e1 = fsum2(acc[1][0]) + bo - xv1;
            g_err[r0 * OUTD + o] = e0;
            g_err[(r0 + 16) * OUTD + o] = e1;
            out[(t * BATCH + r0) * OUTD + o] = e0;
            out[(t * BATCH + r0 + 16) * OUTD + o] = e1;
        }
        barrier_global();

        // ================= Phase C (+ phase-D partials) =================
        // g = err@Wo (via resident woT); eh = 0.1*(1-tp^2)*g; h_post = h_prior-eh
        {
            if (tid == 0) {
                fence_pa();
                mbar_expect(mbar, 32768);
                bulk_g2s(actu, g_err + row0 * OUTD, 32768, mbar);
            }
            mbar_wait(mbar, ph); ph ^= 1;

            u64 acc[2][2] = {};
            gemm_res<2, 2>(sm + OFF_ACT, OUTD, sm + OFF_WOT, SWOT, 4, acc, ty, tx);
#pragma unroll
            for (int im = 0; im < 2; im++)
#pragma unroll
                for (int in = 0; in < 2; in++) {
                    float tp = tpr[im][in];
                    float eh = 0.1f * (1.0f - tp * tp) * fsum2(acc[im][in]);
                    float hnew = hpr[im][in] - eh;
                    hpost[im][in] = hnew;
                    g_th[(row0 + ty + 16 * im) * HID + colA + tx + 16 * in] = tanhf(hnew);
                    sm[OFF_EHS + (ty + 16 * im) * SEH + tx + 16 * in] = eh;
                }
            __syncthreads();   // eh_s tile visible CTA-wide

            // partial of (eh @ Wc) over this CTA's 32-i slice (resident w_c)
            {
                const int r  = tid >> 3;          // 0..31 (local batch row)
                const int c0 = (tid & 7) * 8;     // 8 consecutive causes
                float accD[8] = {};
#pragma unroll 8
                for (int i = 0; i < 32; i++) {
                    float ehv = sm[OFF_EHS + r * SEH + i];
                    const float* w = sm + OFF_WC + i * SWC + c0;
                    float4 w0 = *reinterpret_cast<const float4*>(w);
                    float4 w1 = *reinterpret_cast<const float4*>(w + 4);
                    accD[0] += ehv * w0.x; accD[1] += ehv * w0.y;
                    accD[2] += ehv * w0.z; accD[3] += ehv * w0.w;
                    accD[4] += ehv * w1.x; accD[5] += ehv * w1.y;
                    accD[6] += ehv * w1.z; accD[7] += ehv * w1.w;
                }
                float* dp = g_dpart + bid * 2048 + r * 64 + c0;
                *reinterpret_cast<float4*>(dp)     = make_float4(accD[0], accD[1], accD[2], accD[3]);
                *reinterpret_cast<float4*>(dp + 4) = make_float4(accD[4], accD[5], accD[6], accD[7]);
            }
        }
        barrier_global();

        // ================= Phase D =================
        // c -= 0.1 * sum_j partial_j   (fixed j order -> deterministic)
        if (tid < 128) {
            const int e = q * 128 + tid;          // 0..2047 within group tile
            float s = 0.0f;
#pragma unroll
            for (int j = 0; j < 16; j++)
                s += g_dpart[(grp * 16 + j) * 2048 + e];
            const int r = e >> 6, c = e & 63;
            g_c[(row0 + r) * CAUS + c] -= 0.1f * s;
        }
        barrier_global();
    }
}

// ---------------------------------------------------------------------------
// Launch: single graph-capturable kernel node, no allocation.
// Inputs (metadata order): x, c_init, h_init, w_o, b_o, w_c, w_r, b_r
// ---------------------------------------------------------------------------
extern "C" void kernel_launch(void* const* d_in, const int* in_sizes, int n_in,
                              void* d_out, int out_size) {
    const float* x      = (const float*)d_in[0];
    const float* c_init = (const float*)d_in[1];
    const float* h_init = (const float*)d_in[2];
    const float* w_o    = (const float*)d_in[3];
    const float* b_o    = (const float*)d_in[4];
    const float* w_c    = (const float*)d_in[5];
    const float* w_r    = (const float*)d_in[6];
    const float* b_r    = (const float*)d_in[7];
    float* out = (float*)d_out;

    static int smem_set = 0;
    if (!smem_set) {
        cudaFuncSetAttribute(pc_rnn_kernel,
                             cudaFuncAttributeMaxDynamicSharedMemorySize,
                             SMEM_BYTES);
        smem_set = 1;
    }
    pc_rnn_kernel<<<GRID, NTHREADS, SMEM_BYTES>>>(
        x, c_init, h_init, w_o, b_o, w_c, w_r, b_r, out);
}